// round 1
// baseline (speedup 1.0000x reference)
#include <cuda_runtime.h>
#include <math.h>

#define THREADS 256
static constexpr int S_LEN = 1024;
static constexpr int D_DIM = 512;
static constexpr float LN_EPS = 1e-5f;

__global__ __launch_bounds__(THREADS)
void corr_node_kernel(
    const float* __restrict__ x,
    const float* __restrict__ C,
    const unsigned char* __restrict__ mask,
    const float* __restrict__ proj_w,     // [20, 512]
    const float* __restrict__ proj_b,     // [512]
    const float* __restrict__ ln_gamma,   // [512]
    const float* __restrict__ ln_beta,    // [512]
    const float* __restrict__ gate_p,     // [1]
    const float* __restrict__ rbf_centers,// [8]
    const float* __restrict__ rbf_widths, // [8]
    float* __restrict__ out)
{
    const int row = blockIdx.x;
    const int tid = threadIdx.x;
    const int lane = tid & 31;
    const int warp = tid >> 5;

    __shared__ float s_warp[4][8];
    __shared__ float s_z[20];
    __shared__ float s_mu_rstd[2];

    // ---- prefetch x (float2 per thread: dims 2*tid, 2*tid+1) ----
    const float2* x2 = reinterpret_cast<const float2*>(x + (size_t)row * D_DIM);
    float2 xv = x2[tid];

    // ---- phase 1: C row reduction (sum, sumsq, max, min) ----
    const float4* c4 = reinterpret_cast<const float4*>(C + (size_t)row * S_LEN);
    float4 cv = c4[tid];
    float a0 = fminf(fmaxf(cv.x, 0.f), 1.f);
    float a1 = fminf(fmaxf(cv.y, 0.f), 1.f);
    float a2 = fminf(fmaxf(cv.z, 0.f), 1.f);
    float a3 = fminf(fmaxf(cv.w, 0.f), 1.f);

    float lsum = (a0 + a1) + (a2 + a3);
    float lsq  = (a0*a0 + a1*a1) + (a2*a2 + a3*a3);
    float lmax = fmaxf(fmaxf(a0, a1), fmaxf(a2, a3));
    float lmin = fminf(fminf(a0, a1), fminf(a2, a3));

    #pragma unroll
    for (int off = 16; off > 0; off >>= 1) {
        lsum += __shfl_xor_sync(0xffffffffu, lsum, off);
        lsq  += __shfl_xor_sync(0xffffffffu, lsq,  off);
        lmax = fmaxf(lmax, __shfl_xor_sync(0xffffffffu, lmax, off));
        lmin = fminf(lmin, __shfl_xor_sync(0xffffffffu, lmin, off));
    }
    if (lane == 0) {
        s_warp[0][warp] = lsum;
        s_warp[1][warp] = lsq;
        s_warp[2][warp] = lmax;
        s_warp[3][warp] = lmin;
    }
    __syncthreads();

    if (tid == 0) {
        float tsum = 0.f, tsq = 0.f, tmax = -1e30f, tmin = 1e30f;
        #pragma unroll
        for (int w = 0; w < 8; w++) {
            tsum += s_warp[0][w];
            tsq  += s_warp[1][w];
            tmax = fmaxf(tmax, s_warp[2][w]);
            tmin = fminf(tmin, s_warp[3][w]);
        }
        float mean = tsum * (1.0f / (float)S_LEN);
        float var  = tsq  * (1.0f / (float)S_LEN) - mean * mean;
        float stdv = sqrtf(fmaxf(var, 0.f));
        s_z[0] = mean; s_z[1] = tmax; s_z[2] = tmin; s_z[3] = stdv;
        #pragma unroll
        for (int r = 0; r < 8; r++) {
            float w = rbf_widths[r] + 1e-6f;
            float c = rbf_centers[r];
            float inv_w = __fdividef(1.0f, w);
            float d1 = (mean - c) * inv_w;
            float d2 = (tmax - c) * inv_w;
            s_z[4 + r]  = __expf(-0.5f * d1 * d1);
            s_z[12 + r] = __expf(-0.5f * d2 * d2);
        }
    }
    __syncthreads();

    // ---- phase 2: matvec pe[d] = b[d] + sum_j z[j]*W[j][d], d = 2*tid, 2*tid+1 ----
    const float2* w2 = reinterpret_cast<const float2*>(proj_w);
    const float2* b2 = reinterpret_cast<const float2*>(proj_b);
    float2 bv = __ldg(&b2[tid]);
    float pe0 = bv.x, pe1 = bv.y;
    #pragma unroll
    for (int j = 0; j < 20; j++) {
        float zj = s_z[j];
        float2 wv = __ldg(&w2[j * (D_DIM / 2) + tid]);
        pe0 = fmaf(zj, wv.x, pe0);
        pe1 = fmaf(zj, wv.y, pe1);
    }

    // ---- phase 3: LayerNorm reduce over 512 ----
    float nsum = pe0 + pe1;
    float nsq  = pe0 * pe0 + pe1 * pe1;
    #pragma unroll
    for (int off = 16; off > 0; off >>= 1) {
        nsum += __shfl_xor_sync(0xffffffffu, nsum, off);
        nsq  += __shfl_xor_sync(0xffffffffu, nsq,  off);
    }
    __syncthreads();   // protect s_warp reuse
    if (lane == 0) {
        s_warp[0][warp] = nsum;
        s_warp[1][warp] = nsq;
    }
    __syncthreads();
    if (tid == 0) {
        float tsum = 0.f, tsq = 0.f;
        #pragma unroll
        for (int w = 0; w < 8; w++) { tsum += s_warp[0][w]; tsq += s_warp[1][w]; }
        float mu  = tsum * (1.0f / (float)D_DIM);
        float var = tsq  * (1.0f / (float)D_DIM) - mu * mu;
        s_mu_rstd[0] = mu;
        s_mu_rstd[1] = rsqrtf(var + LN_EPS);
    }
    __syncthreads();

    float mu   = s_mu_rstd[0];
    float rstd = s_mu_rstd[1];
    float g = __ldg(gate_p);
    if (mask[row]) g = 0.0f;

    const float2* gm2 = reinterpret_cast<const float2*>(ln_gamma);
    const float2* bt2 = reinterpret_cast<const float2*>(ln_beta);
    float2 gv = __ldg(&gm2[tid]);
    float2 btv = __ldg(&bt2[tid]);

    float n0 = (pe0 - mu) * rstd * gv.x + btv.x;
    float n1 = (pe1 - mu) * rstd * gv.y + btv.y;

    float2 ov;
    ov.x = xv.x + g * n0;
    ov.y = xv.y + g * n1;
    reinterpret_cast<float2*>(out + (size_t)row * D_DIM)[tid] = ov;
}

extern "C" void kernel_launch(void* const* d_in, const int* in_sizes, int n_in,
                              void* d_out, int out_size) {
    const float* x          = (const float*)d_in[0];
    const float* C          = (const float*)d_in[1];
    const unsigned char* mk = (const unsigned char*)d_in[2];
    const float* proj_w     = (const float*)d_in[3];
    const float* proj_b     = (const float*)d_in[4];
    const float* ln_gamma   = (const float*)d_in[5];
    const float* ln_beta    = (const float*)d_in[6];
    const float* gate       = (const float*)d_in[7];
    const float* rbf_c      = (const float*)d_in[8];
    const float* rbf_w      = (const float*)d_in[9];
    float* out              = (float*)d_out;

    int n_rows = in_sizes[2];   // mask_nodes has N elements

    corr_node_kernel<<<n_rows, THREADS>>>(
        x, C, mk, proj_w, proj_b, ln_gamma, ln_beta, gate, rbf_c, rbf_w, out);
}

// round 2
// speedup vs baseline: 1.5680x; 1.5680x over previous
#include <cuda_runtime.h>
#include <math.h>

#define THREADS 256
#define RPB 4                       // rows per CTA
static constexpr int S_LEN = 1024;
static constexpr int D_DIM = 512;
static constexpr float LN_EPS = 1e-5f;

__global__ __launch_bounds__(THREADS, 5)
void corr_node_kernel(
    const float* __restrict__ x,
    const float* __restrict__ C,
    const unsigned char* __restrict__ mask,
    const float* __restrict__ proj_w,     // [20, 512]
    const float* __restrict__ proj_b,     // [512]
    const float* __restrict__ ln_gamma,   // [512]
    const float* __restrict__ ln_beta,    // [512]
    const float* __restrict__ gate_p,     // [1]
    const float* __restrict__ rbf_centers,// [8]
    const float* __restrict__ rbf_widths, // [8]
    float* __restrict__ out,
    int n_rows)
{
    const int row0 = blockIdx.x * RPB;
    const int tid  = threadIdx.x;
    const int lane = tid & 31;
    const int warp = tid >> 5;
    const int valid = n_rows - row0;     // >= 1 guaranteed

    __shared__ float s_warp[RPB][4][8];
    __shared__ float s_z[RPB][20];
    __shared__ float s_mu[RPB];
    __shared__ float s_rstd[RPB];

    // ---- phase 1: C reductions for RPB contiguous rows ----
    // C[row0 .. row0+RPB) is one contiguous 16KB block; chunk r == row r.
    const float4* c4 = reinterpret_cast<const float4*>(C + (size_t)row0 * S_LEN);
    float4 cv[RPB];
    #pragma unroll
    for (int r = 0; r < RPB; r++) {
        if (r < valid) cv[r] = c4[r * THREADS + tid];
        else           cv[r] = make_float4(0.f, 0.f, 0.f, 0.f);
    }

    #pragma unroll
    for (int r = 0; r < RPB; r++) {
        float a0 = fminf(fmaxf(cv[r].x, 0.f), 1.f);
        float a1 = fminf(fmaxf(cv[r].y, 0.f), 1.f);
        float a2 = fminf(fmaxf(cv[r].z, 0.f), 1.f);
        float a3 = fminf(fmaxf(cv[r].w, 0.f), 1.f);
        float lsum = (a0 + a1) + (a2 + a3);
        float lsq  = (a0*a0 + a1*a1) + (a2*a2 + a3*a3);
        float lmax = fmaxf(fmaxf(a0, a1), fmaxf(a2, a3));
        float lmin = fminf(fminf(a0, a1), fminf(a2, a3));
        #pragma unroll
        for (int off = 16; off > 0; off >>= 1) {
            lsum += __shfl_xor_sync(0xffffffffu, lsum, off);
            lsq  += __shfl_xor_sync(0xffffffffu, lsq,  off);
            lmax = fmaxf(lmax, __shfl_xor_sync(0xffffffffu, lmax, off));
            lmin = fminf(lmin, __shfl_xor_sync(0xffffffffu, lmin, off));
        }
        if (lane == 0) {
            s_warp[r][0][warp] = lsum;
            s_warp[r][1][warp] = lsq;
            s_warp[r][2][warp] = lmax;
            s_warp[r][3][warp] = lmin;
        }
    }
    __syncthreads();

    // ---- finalize stats + RBF features: thread r handles row r ----
    if (tid < RPB) {
        const int r = tid;
        float tsum = 0.f, tsq = 0.f, tmax = -1e30f, tmin = 1e30f;
        #pragma unroll
        for (int w = 0; w < 8; w++) {
            tsum += s_warp[r][0][w];
            tsq  += s_warp[r][1][w];
            tmax = fmaxf(tmax, s_warp[r][2][w]);
            tmin = fminf(tmin, s_warp[r][3][w]);
        }
        float mean = tsum * (1.0f / (float)S_LEN);
        float var  = tsq  * (1.0f / (float)S_LEN) - mean * mean;
        float stdv = sqrtf(fmaxf(var, 0.f));
        s_z[r][0] = mean; s_z[r][1] = tmax; s_z[r][2] = tmin; s_z[r][3] = stdv;
        #pragma unroll
        for (int k = 0; k < 8; k++) {
            float w = __ldg(&rbf_widths[k]) + 1e-6f;
            float c = __ldg(&rbf_centers[k]);
            float inv_w = __fdividef(1.0f, w);
            float d1 = (mean - c) * inv_w;
            float d2 = (tmax - c) * inv_w;
            s_z[r][4 + k]  = __expf(-0.5f * d1 * d1);
            s_z[r][12 + k] = __expf(-0.5f * d2 * d2);
        }
    }
    __syncthreads();

    // ---- phase 2: matvec, dims d = 2*tid, 2*tid+1 for all RPB rows ----
    const float2* w2 = reinterpret_cast<const float2*>(proj_w);
    const float2* b2 = reinterpret_cast<const float2*>(proj_b);
    float2 bv = __ldg(&b2[tid]);
    float pe0[RPB], pe1[RPB];
    #pragma unroll
    for (int r = 0; r < RPB; r++) { pe0[r] = bv.x; pe1[r] = bv.y; }

    #pragma unroll
    for (int j = 0; j < 20; j++) {
        float2 wv = __ldg(&w2[j * (D_DIM / 2) + tid]);
        #pragma unroll
        for (int r = 0; r < RPB; r++) {
            float zj = s_z[r][j];
            pe0[r] = fmaf(zj, wv.x, pe0[r]);
            pe1[r] = fmaf(zj, wv.y, pe1[r]);
        }
    }

    // ---- phase 3: LayerNorm reductions (per row) ----
    #pragma unroll
    for (int r = 0; r < RPB; r++) {
        float nsum = pe0[r] + pe1[r];
        float nsq  = pe0[r]*pe0[r] + pe1[r]*pe1[r];
        #pragma unroll
        for (int off = 16; off > 0; off >>= 1) {
            nsum += __shfl_xor_sync(0xffffffffu, nsum, off);
            nsq  += __shfl_xor_sync(0xffffffffu, nsq,  off);
        }
        if (lane == 0) {
            s_warp[r][0][warp] = nsum;
            s_warp[r][1][warp] = nsq;
        }
    }
    __syncthreads();
    if (tid < RPB) {
        const int r = tid;
        float tsum = 0.f, tsq = 0.f;
        #pragma unroll
        for (int w = 0; w < 8; w++) { tsum += s_warp[r][0][w]; tsq += s_warp[r][1][w]; }
        float mu  = tsum * (1.0f / (float)D_DIM);
        float var = tsq  * (1.0f / (float)D_DIM) - mu * mu;
        s_mu[r]   = mu;
        s_rstd[r] = rsqrtf(var + LN_EPS);
    }
    __syncthreads();

    // ---- phase 4: affine + gate + mask + residual add, write out ----
    const float2* gm2 = reinterpret_cast<const float2*>(ln_gamma);
    const float2* bt2 = reinterpret_cast<const float2*>(ln_beta);
    float2 gv  = __ldg(&gm2[tid]);
    float2 btv = __ldg(&bt2[tid]);
    float gate = __ldg(gate_p);

    const float2* x2 = reinterpret_cast<const float2*>(x + (size_t)row0 * D_DIM);
    float2* o2       = reinterpret_cast<float2*>(out + (size_t)row0 * D_DIM);

    #pragma unroll
    for (int r = 0; r < RPB; r++) {
        if (r >= valid) break;
        float g = mask[row0 + r] ? 0.0f : gate;
        float mu = s_mu[r], rstd = s_rstd[r];
        float2 xv = x2[r * (D_DIM / 2) + tid];
        float n0 = (pe0[r] - mu) * rstd * gv.x + btv.x;
        float n1 = (pe1[r] - mu) * rstd * gv.y + btv.y;
        float2 ov;
        ov.x = xv.x + g * n0;
        ov.y = xv.y + g * n1;
        o2[r * (D_DIM / 2) + tid] = ov;
    }
}

extern "C" void kernel_launch(void* const* d_in, const int* in_sizes, int n_in,
                              void* d_out, int out_size) {
    const float* x          = (const float*)d_in[0];
    const float* C          = (const float*)d_in[1];
    const unsigned char* mk = (const unsigned char*)d_in[2];
    const float* proj_w     = (const float*)d_in[3];
    const float* proj_b     = (const float*)d_in[4];
    const float* ln_gamma   = (const float*)d_in[5];
    const float* ln_beta    = (const float*)d_in[6];
    const float* gate       = (const float*)d_in[7];
    const float* rbf_c      = (const float*)d_in[8];
    const float* rbf_w      = (const float*)d_in[9];
    float* out              = (float*)d_out;

    int n_rows = in_sizes[2];   // mask_nodes has N elements
    int grid = (n_rows + RPB - 1) / RPB;

    corr_node_kernel<<<grid, THREADS>>>(
        x, C, mk, proj_w, proj_b, ln_gamma, ln_beta, gate, rbf_c, rbf_w, out, n_rows);
}